// round 14
// baseline (speedup 1.0000x reference)
#include <cuda_runtime.h>
#include <cuda_fp16.h>
#include <cstdint>
#include <cstring>

// ---------------------------------------------------------------------------
// Problem constants
// ---------------------------------------------------------------------------
#define BATCH   1568
#define NTOK    64
#define CDIM    512
#define HEADS   16
#define HD      32
#define NW      49
#define MTOT    (BATCH * NTOK)          // 100352
#define QKVN    (3 * CDIM)              // 1536

#define NCHUNK  4
#define BCH     (BATCH / NCHUNK)        // 392 windows per chunk
#define MCH     (BCH * NTOK)            // 25088 rows per chunk

// ---------------------------------------------------------------------------
// Device scratch (static globals: allocation-free per harness rules)
// ---------------------------------------------------------------------------
__device__ __half g_qkvh[(size_t)MTOT * QKVN];      // qkv projection output (fp16)
__device__ __half g_att[(size_t)MTOT * CDIM];       // attention output (fp16)
__device__ __half g_x  [(size_t)MTOT * CDIM];       // fp16 input x
__device__ __half g_wq [(size_t)QKVN * CDIM];       // fp16 qkv_w
__device__ __half g_wp [(size_t)CDIM * CDIM];       // fp16 proj_w
__device__ float  g_bm [HEADS * NW * NTOK * NTOK];  // fused bias+mask (h,w,64,64)
__device__ float  g_tbl[225 * HEADS];               // CRPB table
__device__ float  g_scale[HEADS];                   // clamped temperature per head

// ---------------------------------------------------------------------------
// helpers
// ---------------------------------------------------------------------------
__device__ __forceinline__ uint32_t h2_as_u32(__half2 h) {
    uint32_t u;
    memcpy(&u, &h, 4);
    return u;
}

__device__ __forceinline__ void mma_f16(float* c, const uint32_t* a, const uint32_t* b) {
    asm volatile(
        "mma.sync.aligned.m16n8k16.row.col.f32.f16.f16.f32 "
        "{%0,%1,%2,%3}, {%4,%5,%6,%7}, {%8,%9}, {%0,%1,%2,%3};"
        : "+f"(c[0]), "+f"(c[1]), "+f"(c[2]), "+f"(c[3])
        : "r"(a[0]), "r"(a[1]), "r"(a[2]), "r"(a[3]),
          "r"(b[0]), "r"(b[1]));
}

__device__ __forceinline__ void ldsm_x4(uint32_t* r, const __half* p) {
    uint32_t addr = (uint32_t)__cvta_generic_to_shared(p);
    asm volatile("ldmatrix.sync.aligned.m8n8.x4.shared.b16 {%0,%1,%2,%3}, [%4];"
                 : "=r"(r[0]), "=r"(r[1]), "=r"(r[2]), "=r"(r[3]) : "r"(addr));
}

__device__ __forceinline__ void ldsm_x4_trans(uint32_t* r, const __half* p) {
    uint32_t addr = (uint32_t)__cvta_generic_to_shared(p);
    asm volatile("ldmatrix.sync.aligned.m8n8.x4.trans.shared.b16 {%0,%1,%2,%3}, [%4];"
                 : "=r"(r[0]), "=r"(r[1]), "=r"(r[2]), "=r"(r[3]) : "r"(addr));
}

__device__ __forceinline__ void cp16(uint32_t saddr, const void* g) {
    asm volatile("cp.async.ca.shared.global [%0], [%1], 16;" :: "r"(saddr), "l"(g));
}
__device__ __forceinline__ void cp_commit() {
    asm volatile("cp.async.commit_group;");
}
template <int N>
__device__ __forceinline__ void cp_wait() {
    asm volatile("cp.async.wait_group %0;" :: "n"(N));
}

// ---------------------------------------------------------------------------
// Kernel 0: elementwise fp32 -> fp16 conversion
// ---------------------------------------------------------------------------
__global__ void to_half_kernel(const float* __restrict__ in,
                               __half* __restrict__ out, int n4)
{
    int i = blockIdx.x * blockDim.x + threadIdx.x;
    if (i >= n4) return;
    float4 v = ((const float4*)in)[i];
    ((__half2*)out)[i * 2 + 0] = __floats2half2_rn(v.x, v.y);
    ((__half2*)out)[i * 2 + 1] = __floats2half2_rn(v.z, v.w);
}

// ---------------------------------------------------------------------------
// Kernel 1a: CRPB MLP table + temperature scale
// ---------------------------------------------------------------------------
__global__ void crpb_tbl_kernel(const float* __restrict__ ct,
                                const float* __restrict__ w1,
                                const float* __restrict__ b1,
                                const float* __restrict__ w2,
                                const float* __restrict__ ts)
{
    int e = threadIdx.x;
    if (e < HEADS) {
        g_scale[e] = expf(fminf(ts[e], 4.6051701859880913680f));
    }
    if (e < 225) {
        float c0 = ct[e * 2 + 0];
        float c1 = ct[e * 2 + 1];
        float acc[HEADS];
#pragma unroll
        for (int h = 0; h < HEADS; h++) acc[h] = 0.f;
        for (int j = 0; j < 384; j++) {
            float hv = fmaxf(w1[j * 2 + 0] * c0 + w1[j * 2 + 1] * c1 + b1[j], 0.f);
#pragma unroll
            for (int h = 0; h < HEADS; h++) acc[h] += w2[h * 384 + j] * hv;
        }
#pragma unroll
        for (int h = 0; h < HEADS; h++) g_tbl[e * HEADS + h] = acc[h];
    }
}

// ---------------------------------------------------------------------------
// Kernel 1b: fused bias+mask table
// ---------------------------------------------------------------------------
__global__ void bm_fill_kernel(const int* __restrict__ ridx,
                               const float* __restrict__ mask)
{
    int t = blockIdx.x * blockDim.x + threadIdx.x;
    int ij = t & 4095;
    int hw = t >> 12;
    int w  = hw % NW;
    int h  = hw / NW;
    float v = g_tbl[ridx[ij] * HEADS + h];
    g_bm[t] = 16.f / (1.f + __expf(-v)) + mask[w * 4096 + ij];
}

// ---------------------------------------------------------------------------
// Kernel 2/4: fp16 mma.sync GEMM (fp32 accumulate), templated output type.
// (identical to R13 passing version)
// ---------------------------------------------------------------------------
#define BM 128
#define BN 128
#define BKT 64
#define STAGES 3
#define GEMM_SMEM (STAGES * (BM + BN) * BKT * 2)   // 98304 bytes

template <typename OutT>
__global__ __launch_bounds__(128, 2)
void gemm_f16_abT(const __half* __restrict__ A, const __half* __restrict__ B,
                  const float* __restrict__ bias, OutT* __restrict__ C,
                  int M, int N, int K)
{
    extern __shared__ __half smh[];
    __half* AsBase = smh;
    __half* BsBase = smh + STAGES * BM * BKT;
    const uint32_t smemA_u32 = (uint32_t)__cvta_generic_to_shared(AsBase);
    const uint32_t smemB_u32 = (uint32_t)__cvta_generic_to_shared(BsBase);

    const int tid  = threadIdx.x;
    const int bm   = blockIdx.y * BM;
    const int bn   = blockIdx.x * BN;
    const int warp = tid >> 5;
    const int lane = tid & 31;
    const int wm   = (warp & 1) * 64;
    const int wn   = (warp >> 1) * 64;
    const int g    = lane >> 2;
    const int t4   = lane & 3;

    const int lt = lane >> 3;
    const int lr = lane & 7;
    const int a_row_l = wm + (lt & 1) * 8 + lr;
    const int a_chk_l = lt >> 1;
    const int b_row_l = wn + (lt >> 1) * 8 + lr;
    const int b_chk_l = lt & 1;

    float acc[4][8][4];
#pragma unroll
    for (int im = 0; im < 4; im++)
#pragma unroll
        for (int in = 0; in < 8; in++)
#pragma unroll
            for (int r = 0; r < 4; r++) acc[im][in][r] = 0.f;

    const int NIT = K / BKT;

    auto issue = [&](int stage, int kt) {
        const int kbase = kt * BKT;
#pragma unroll
        for (int l = 0; l < 8; l++) {
            int f    = tid + l * 128;
            int row  = f >> 3;
            int chk  = f & 7;
            int sc   = (chk ^ (row & 7)) * 8;
            cp16(smemA_u32 + (uint32_t)(stage * BM * BKT + row * BKT + sc) * 2,
                 A + (size_t)(bm + row) * K + kbase + chk * 8);
            cp16(smemB_u32 + (uint32_t)(stage * BN * BKT + row * BKT + sc) * 2,
                 B + (size_t)(bn + row) * K + kbase + chk * 8);
        }
    };

    issue(0, 0); cp_commit();
    issue(1, 1); cp_commit();

    for (int it = 0; it < NIT; it++) {
        const int s = it % STAGES;
        cp_wait<1>();
        __syncthreads();

        if (it + 2 < NIT) issue((it + 2) % STAGES, it + 2);
        cp_commit();

        const __half* Ast = AsBase + s * BM * BKT;
        const __half* Bst = BsBase + s * BN * BKT;

        uint32_t af[2][4][4], bf[2][16];

        auto ldfrag = [&](int buf, int kc) {
#pragma unroll
            for (int im = 0; im < 4; im++) {
                int row = a_row_l + im * 16;
                int chk = kc + a_chk_l;
                ldsm_x4(af[buf][im], Ast + row * BKT + ((chk ^ (row & 7)) * 8));
            }
#pragma unroll
            for (int n16 = 0; n16 < 4; n16++) {
                int row = b_row_l + n16 * 16;
                int chk = kc + b_chk_l;
                ldsm_x4(bf[buf] + n16 * 4, Bst + row * BKT + ((chk ^ (row & 7)) * 8));
            }
        };

        ldfrag(0, 0);
#pragma unroll
        for (int ks = 0; ks < 4; ks++) {
            const int cur = ks & 1;
            if (ks < 3) ldfrag(cur ^ 1, (ks + 1) * 2);
#pragma unroll
            for (int im = 0; im < 4; im++)
#pragma unroll
                for (int in = 0; in < 8; in++)
                    mma_f16(acc[im][in], af[cur][im], bf[cur] + in * 2);
        }
    }

#pragma unroll
    for (int im = 0; im < 4; im++) {
#pragma unroll
        for (int in = 0; in < 8; in++) {
            int r = bm + wm + im * 16 + g;
            int c = bn + wn + in * 8 + t4 * 2;
            float b0 = bias[c];
            float b1 = bias[c + 1];
            float v00 = acc[im][in][0] + b0, v01 = acc[im][in][1] + b1;
            float v10 = acc[im][in][2] + b0, v11 = acc[im][in][3] + b1;
            if constexpr (sizeof(OutT) == 4) {
                *(float2*)((float*)C + (size_t)r * N + c)       = make_float2(v00, v01);
                *(float2*)((float*)C + (size_t)(r + 8) * N + c) = make_float2(v10, v11);
            } else {
                *(__half2*)((__half*)C + (size_t)r * N + c)       = __floats2half2_rn(v00, v01);
                *(__half2*)((__half*)C + (size_t)(r + 8) * N + c) = __floats2half2_rn(v10, v11);
            }
        }
    }
}

// ---------------------------------------------------------------------------
// Kernel 3: tensor-core attention. One block (128 thr, 4 warps) per (b,h).
// bh0: global (window,head) offset of this chunk.
// ---------------------------------------------------------------------------
__global__ __launch_bounds__(128)
void attn_mma_kernel(__half* __restrict__ out, int bh0)
{
    const int bh = bh0 + blockIdx.x;
    const int b  = bh >> 4;
    const int h  = bh & 15;
    const int w  = b % NW;

    __shared__ __half Qs[64][40];
    __shared__ __half Ks[64][40];
    __shared__ __half Vs[64][40];

    const int tid  = threadIdx.x;
    const int warp = tid >> 5;
    const int lane = tid & 31;

    {
        const __half* base = g_qkvh + (size_t)b * NTOK * QKVN + h * HD;
        int tok = tid >> 1;
        int p   = tid & 1;
        const uint4* qp = (const uint4*)(base + (size_t)tok * QKVN);
        const uint4* kp = (const uint4*)(base + (size_t)tok * QKVN + 512);
        const uint4* vp = (const uint4*)(base + (size_t)tok * QKVN + 1024);
        *(uint4*)&Qs[tok][p * 16 + 0] = qp[p * 2 + 0];
        *(uint4*)&Qs[tok][p * 16 + 8] = qp[p * 2 + 1];
        *(uint4*)&Ks[tok][p * 16 + 0] = kp[p * 2 + 0];
        *(uint4*)&Ks[tok][p * 16 + 8] = kp[p * 2 + 1];
        *(uint4*)&Vs[tok][p * 16 + 0] = vp[p * 2 + 0];
        *(uint4*)&Vs[tok][p * 16 + 8] = vp[p * 2 + 1];
    }
    __syncthreads();

    {
        int r = tid & 63;
        __half* row = (tid < 64) ? Qs[r] : Ks[r];
        float f[32];
        float s = 0.f;
#pragma unroll
        for (int i = 0; i < 16; i++) {
            float2 v = __half22float2(*(__half2*)&row[i * 2]);
            f[i * 2] = v.x; f[i * 2 + 1] = v.y;
            s += v.x * v.x + v.y * v.y;
        }
        float inv = 1.0f / fmaxf(sqrtf(s), 1e-12f);
        if (tid < 64) inv *= g_scale[h];
#pragma unroll
        for (int i = 0; i < 16; i++)
            *(__half2*)&row[i * 2] = __floats2half2_rn(f[i * 2] * inv, f[i * 2 + 1] * inv);
    }
    __syncthreads();

    const int lt = lane >> 3;
    const int lr = lane & 7;
    const int g  = lane >> 2;
    const int t4 = lane & 3;
    const int r0 = warp * 16;
    const int r_lo = r0 + g;
    const int r_hi = r0 + 8 + g;

    // prefetch bias+mask into registers (overlaps with S MMAs below)
    const float* bmp = g_bm + (((size_t)h * NW + w) << 12);
    float2 blo[8], bhi[8];
#pragma unroll
    for (int t = 0; t < 8; t++) {
        int col = t * 8 + t4 * 2;
        blo[t] = *(const float2*)&bmp[r_lo * 64 + col];
        bhi[t] = *(const float2*)&bmp[r_hi * 64 + col];
    }

    float sacc[8][4];
#pragma unroll
    for (int t = 0; t < 8; t++)
#pragma unroll
        for (int r = 0; r < 4; r++) sacc[t][r] = 0.f;

#pragma unroll
    for (int ks = 0; ks < 2; ks++) {
        uint32_t af[4];
        ldsm_x4(af, &Qs[r0 + (lt & 1) * 8 + lr][(lt >> 1) * 8 + ks * 16]);
#pragma unroll
        for (int ng = 0; ng < 4; ng++) {
            uint32_t bfk[4];
            ldsm_x4(bfk, &Ks[ng * 16 + (lt >> 1) * 8 + lr][(lt & 1) * 8 + ks * 16]);
            mma_f16(sacc[ng * 2 + 0], af, bfk);
            mma_f16(sacc[ng * 2 + 1], af, bfk + 2);
        }
    }

#pragma unroll
    for (int t = 0; t < 8; t++) {
        sacc[t][0] += blo[t].x; sacc[t][1] += blo[t].y;
        sacc[t][2] += bhi[t].x; sacc[t][3] += bhi[t].y;
    }

    float mlo = -1e30f, mhi = -1e30f;
#pragma unroll
    for (int t = 0; t < 8; t++) {
        mlo = fmaxf(mlo, fmaxf(sacc[t][0], sacc[t][1]));
        mhi = fmaxf(mhi, fmaxf(sacc[t][2], sacc[t][3]));
    }
    mlo = fmaxf(mlo, __shfl_xor_sync(0xffffffffu, mlo, 1));
    mlo = fmaxf(mlo, __shfl_xor_sync(0xffffffffu, mlo, 2));
    mhi = fmaxf(mhi, __shfl_xor_sync(0xffffffffu, mhi, 1));
    mhi = fmaxf(mhi, __shfl_xor_sync(0xffffffffu, mhi, 2));

    float slo = 0.f, shi = 0.f;
#pragma unroll
    for (int t = 0; t < 8; t++) {
        sacc[t][0] = __expf(sacc[t][0] - mlo);
        sacc[t][1] = __expf(sacc[t][1] - mlo);
        sacc[t][2] = __expf(sacc[t][2] - mhi);
        sacc[t][3] = __expf(sacc[t][3] - mhi);
        slo += sacc[t][0] + sacc[t][1];
        shi += sacc[t][2] + sacc[t][3];
    }
    slo += __shfl_xor_sync(0xffffffffu, slo, 1);
    slo += __shfl_xor_sync(0xffffffffu, slo, 2);
    shi += __shfl_xor_sync(0xffffffffu, shi, 1);
    shi += __shfl_xor_sync(0xffffffffu, shi, 2);
    const float ilo = 1.0f / slo;
    const float ihi = 1.0f / shi;

    uint32_t p01[8], p23[8];
#pragma unroll
    for (int t = 0; t < 8; t++) {
        p01[t] = h2_as_u32(__floats2half2_rn(sacc[t][0] * ilo, sacc[t][1] * ilo));
        p23[t] = h2_as_u32(__floats2half2_rn(sacc[t][2] * ihi, sacc[t][3] * ihi));
    }

    float oacc[4][4];
#pragma unroll
    for (int t = 0; t < 4; t++)
#pragma unroll
        for (int r = 0; r < 4; r++) oacc[t][r] = 0.f;

#pragma unroll
    for (int kg = 0; kg < 4; kg++) {
        uint32_t af[4] = { p01[kg * 2], p23[kg * 2], p01[kg * 2 + 1], p23[kg * 2 + 1] };
        uint32_t bf0[4], bf1[4];
        ldsm_x4_trans(bf0, &Vs[kg * 16 + (lt & 1) * 8 + lr][(lt >> 1) * 8]);
        ldsm_x4_trans(bf1, &Vs[kg * 16 + (lt & 1) * 8 + lr][(lt >> 1) * 8 + 16]);
        mma_f16(oacc[0], af, bf0);
        mma_f16(oacc[1], af, bf0 + 2);
        mma_f16(oacc[2], af, bf1);
        mma_f16(oacc[3], af, bf1 + 2);
    }

    __half* ob = out + ((size_t)b * NTOK) * CDIM + h * HD;
#pragma unroll
    for (int t = 0; t < 4; t++) {
        int col = t * 8 + t4 * 2;
        *(__half2*)(ob + (size_t)r_lo * CDIM + col) = __floats2half2_rn(oacc[t][0], oacc[t][1]);
        *(__half2*)(ob + (size_t)r_hi * CDIM + col) = __floats2half2_rn(oacc[t][2], oacc[t][3]);
    }
}

// ---------------------------------------------------------------------------
// Launch: chunked fork-join pipeline.
// Origin stream: prep + QKV chunks. Side stream s2: attn+proj per chunk,
// forked after each QKV chunk's event, joined at the end.
// ---------------------------------------------------------------------------
extern "C" void kernel_launch(void* const* d_in, const int* in_sizes, int n_in,
                              void* d_out, int out_size)
{
    const float* x        = (const float*)d_in[0];
    const float* mask     = (const float*)d_in[1];
    const float* qkv_w    = (const float*)d_in[2];
    const float* qkv_b    = (const float*)d_in[3];
    const float* proj_w   = (const float*)d_in[4];
    const float* proj_b   = (const float*)d_in[5];
    const float* t_scale  = (const float*)d_in[6];
    const float* crpb_w1  = (const float*)d_in[7];
    const float* crpb_b1  = (const float*)d_in[8];
    const float* crpb_w2  = (const float*)d_in[9];
    const float* ctable   = (const float*)d_in[10];
    const int*   rel_idx  = (const int*)d_in[11];
    float*       out      = (float*)d_out;

    __half *qkvh, *att, *xh, *wq, *wp;
    cudaGetSymbolAddress((void**)&qkvh, g_qkvh);
    cudaGetSymbolAddress((void**)&att,  g_att);
    cudaGetSymbolAddress((void**)&xh,   g_x);
    cudaGetSymbolAddress((void**)&wq,   g_wq);
    cudaGetSymbolAddress((void**)&wp,   g_wp);

    static bool init_done = false;
    static cudaStream_t s2;
    static cudaEvent_t evQ[NCHUNK], evJoin;
    if (!init_done) {
        cudaFuncSetAttribute(gemm_f16_abT<__half>,
                             cudaFuncAttributeMaxDynamicSharedMemorySize, GEMM_SMEM);
        cudaFuncSetAttribute(gemm_f16_abT<float>,
                             cudaFuncAttributeMaxDynamicSharedMemorySize, GEMM_SMEM);
        cudaStreamCreateWithFlags(&s2, cudaStreamNonBlocking);
        for (int c = 0; c < NCHUNK; c++)
            cudaEventCreateWithFlags(&evQ[c], cudaEventDisableTiming);
        cudaEventCreateWithFlags(&evJoin, cudaEventDisableTiming);
        init_done = true;
    }

    // prep on origin stream
    crpb_tbl_kernel<<<1, 256>>>(ctable, crpb_w1, crpb_b1, crpb_w2, t_scale);
    bm_fill_kernel<<<(HEADS * NW * 4096) / 256, 256>>>(rel_idx, mask);
    {
        int n4x = MTOT * CDIM / 4;
        to_half_kernel<<<(n4x + 255) / 256, 256>>>(x, xh, n4x);
        int n4q = QKVN * CDIM / 4;
        to_half_kernel<<<(n4q + 255) / 256, 256>>>(qkv_w, wq, n4q);
        int n4p = CDIM * CDIM / 4;
        to_half_kernel<<<(n4p + 255) / 256, 256>>>(proj_w, wp, n4p);
    }

    // chunked pipeline
    for (int c = 0; c < NCHUNK; c++) {
        const size_t rowoff = (size_t)c * MCH;
        // QKV chunk on origin stream
        {
            dim3 grid(QKVN / BN, MCH / BM);
            gemm_f16_abT<__half><<<grid, 128, GEMM_SMEM>>>(
                xh + rowoff * CDIM, wq, qkv_b, qkvh + rowoff * QKVN,
                MCH, QKVN, CDIM);
        }
        cudaEventRecord(evQ[c], 0);
        cudaStreamWaitEvent(s2, evQ[c], 0);
        // attn + proj chunk on side stream
        attn_mma_kernel<<<BCH * HEADS, 128, 0, s2>>>(att, c * BCH * HEADS);
        {
            dim3 grid(CDIM / BN, MCH / BM);
            gemm_f16_abT<float><<<grid, 128, GEMM_SMEM, s2>>>(
                att + rowoff * CDIM, wp, proj_b, out + rowoff * CDIM,
                MCH, CDIM, CDIM);
        }
    }
    cudaEventRecord(evJoin, s2);
    cudaStreamWaitEvent(0, evJoin, 0);
}

// round 15
// speedup vs baseline: 1.0040x; 1.0040x over previous
#include <cuda_runtime.h>
#include <cuda_fp16.h>
#include <cstdint>
#include <cstring>

// ---------------------------------------------------------------------------
// Problem constants
// ---------------------------------------------------------------------------
#define BATCH   1568
#define NTOK    64
#define CDIM    512
#define HEADS   16
#define HD      32
#define NW      49
#define MTOT    (BATCH * NTOK)          // 100352
#define QKVN    (3 * CDIM)              // 1536

#define NCHUNK  4
#define BCH     (BATCH / NCHUNK)        // 392 windows per chunk
#define MCH     (BCH * NTOK)            // 25088 rows per chunk

// ---------------------------------------------------------------------------
// Device scratch (static globals: allocation-free per harness rules)
// ---------------------------------------------------------------------------
__device__ __half g_qkvh[(size_t)MTOT * QKVN];      // qkv projection output (fp16)
__device__ __half g_att[(size_t)MTOT * CDIM];       // attention output (fp16)
__device__ __half g_x  [(size_t)MTOT * CDIM];       // fp16 input x
__device__ __half g_wq [(size_t)QKVN * CDIM];       // fp16 qkv_w
__device__ __half g_wp [(size_t)CDIM * CDIM];       // fp16 proj_w
__device__ float  g_bm [HEADS * NW * NTOK * NTOK];  // fused bias+mask (h,w,64,64)
__device__ float  g_tbl[225 * HEADS];               // CRPB table
__device__ float  g_scale[HEADS];                   // clamped temperature per head

// ---------------------------------------------------------------------------
// helpers
// ---------------------------------------------------------------------------
__device__ __forceinline__ uint32_t h2_as_u32(__half2 h) {
    uint32_t u;
    memcpy(&u, &h, 4);
    return u;
}

__device__ __forceinline__ void mma_f16(float* c, const uint32_t* a, const uint32_t* b) {
    asm volatile(
        "mma.sync.aligned.m16n8k16.row.col.f32.f16.f16.f32 "
        "{%0,%1,%2,%3}, {%4,%5,%6,%7}, {%8,%9}, {%0,%1,%2,%3};"
        : "+f"(c[0]), "+f"(c[1]), "+f"(c[2]), "+f"(c[3])
        : "r"(a[0]), "r"(a[1]), "r"(a[2]), "r"(a[3]),
          "r"(b[0]), "r"(b[1]));
}

__device__ __forceinline__ void ldsm_x4(uint32_t* r, const __half* p) {
    uint32_t addr = (uint32_t)__cvta_generic_to_shared(p);
    asm volatile("ldmatrix.sync.aligned.m8n8.x4.shared.b16 {%0,%1,%2,%3}, [%4];"
                 : "=r"(r[0]), "=r"(r[1]), "=r"(r[2]), "=r"(r[3]) : "r"(addr));
}

__device__ __forceinline__ void ldsm_x4_trans(uint32_t* r, const __half* p) {
    uint32_t addr = (uint32_t)__cvta_generic_to_shared(p);
    asm volatile("ldmatrix.sync.aligned.m8n8.x4.trans.shared.b16 {%0,%1,%2,%3}, [%4];"
                 : "=r"(r[0]), "=r"(r[1]), "=r"(r[2]), "=r"(r[3]) : "r"(addr));
}

__device__ __forceinline__ void cp16(uint32_t saddr, const void* g) {
    asm volatile("cp.async.ca.shared.global [%0], [%1], 16;" :: "r"(saddr), "l"(g));
}
__device__ __forceinline__ void cp_commit() {
    asm volatile("cp.async.commit_group;");
}
template <int N>
__device__ __forceinline__ void cp_wait() {
    asm volatile("cp.async.wait_group %0;" :: "n"(N));
}

// ---------------------------------------------------------------------------
// Kernel 0: elementwise fp32 -> fp16 conversion
// ---------------------------------------------------------------------------
__global__ void to_half_kernel(const float* __restrict__ in,
                               __half* __restrict__ out, int n4)
{
    int i = blockIdx.x * blockDim.x + threadIdx.x;
    if (i >= n4) return;
    float4 v = ((const float4*)in)[i];
    ((__half2*)out)[i * 2 + 0] = __floats2half2_rn(v.x, v.y);
    ((__half2*)out)[i * 2 + 1] = __floats2half2_rn(v.z, v.w);
}

// ---------------------------------------------------------------------------
// Kernel 1a: CRPB MLP table + temperature scale
// ---------------------------------------------------------------------------
__global__ void crpb_tbl_kernel(const float* __restrict__ ct,
                                const float* __restrict__ w1,
                                const float* __restrict__ b1,
                                const float* __restrict__ w2,
                                const float* __restrict__ ts)
{
    int e = threadIdx.x;
    if (e < HEADS) {
        g_scale[e] = expf(fminf(ts[e], 4.6051701859880913680f));
    }
    if (e < 225) {
        float c0 = ct[e * 2 + 0];
        float c1 = ct[e * 2 + 1];
        float acc[HEADS];
#pragma unroll
        for (int h = 0; h < HEADS; h++) acc[h] = 0.f;
        for (int j = 0; j < 384; j++) {
            float hv = fmaxf(w1[j * 2 + 0] * c0 + w1[j * 2 + 1] * c1 + b1[j], 0.f);
#pragma unroll
            for (int h = 0; h < HEADS; h++) acc[h] += w2[h * 384 + j] * hv;
        }
#pragma unroll
        for (int h = 0; h < HEADS; h++) g_tbl[e * HEADS + h] = acc[h];
    }
}

// ---------------------------------------------------------------------------
// Kernel 1b: fused bias+mask table
// ---------------------------------------------------------------------------
__global__ void bm_fill_kernel(const int* __restrict__ ridx,
                               const float* __restrict__ mask)
{
    int t = blockIdx.x * blockDim.x + threadIdx.x;
    int ij = t & 4095;
    int hw = t >> 12;
    int w  = hw % NW;
    int h  = hw / NW;
    float v = g_tbl[ridx[ij] * HEADS + h];
    g_bm[t] = 16.f / (1.f + __expf(-v)) + mask[w * 4096 + ij];
}

// ---------------------------------------------------------------------------
// Kernel 2/4: fp16 mma.sync GEMM (fp32 accumulate), templated output type.
// (identical math to R13 passing version)
// ---------------------------------------------------------------------------
#define BM 128
#define BN 128
#define BKT 64
#define STAGES 3
#define GEMM_SMEM (STAGES * (BM + BN) * BKT * 2)   // 98304 bytes

template <typename OutT>
__global__ __launch_bounds__(128, 2)
void gemm_f16_abT(const __half* __restrict__ A, const __half* __restrict__ B,
                  const float* __restrict__ bias, OutT* __restrict__ C,
                  int M, int N, int K)
{
    extern __shared__ __half smh[];
    __half* AsBase = smh;
    __half* BsBase = smh + STAGES * BM * BKT;
    const uint32_t smemA_u32 = (uint32_t)__cvta_generic_to_shared(AsBase);
    const uint32_t smemB_u32 = (uint32_t)__cvta_generic_to_shared(BsBase);

    const int tid  = threadIdx.x;
    const int bm   = blockIdx.y * BM;
    const int bn   = blockIdx.x * BN;
    const int warp = tid >> 5;
    const int lane = tid & 31;
    const int wm   = (warp & 1) * 64;
    const int wn   = (warp >> 1) * 64;
    const int g    = lane >> 2;
    const int t4   = lane & 3;

    const int lt = lane >> 3;
    const int lr = lane & 7;
    const int a_row_l = wm + (lt & 1) * 8 + lr;
    const int a_chk_l = lt >> 1;
    const int b_row_l = wn + (lt >> 1) * 8 + lr;
    const int b_chk_l = lt & 1;

    float acc[4][8][4];
#pragma unroll
    for (int im = 0; im < 4; im++)
#pragma unroll
        for (int in = 0; in < 8; in++)
#pragma unroll
            for (int r = 0; r < 4; r++) acc[im][in][r] = 0.f;

    const int NIT = K / BKT;

    auto issue = [&](int stage, int kt) {
        const int kbase = kt * BKT;
#pragma unroll
        for (int l = 0; l < 8; l++) {
            int f    = tid + l * 128;
            int row  = f >> 3;
            int chk  = f & 7;
            int sc   = (chk ^ (row & 7)) * 8;
            cp16(smemA_u32 + (uint32_t)(stage * BM * BKT + row * BKT + sc) * 2,
                 A + (size_t)(bm + row) * K + kbase + chk * 8);
            cp16(smemB_u32 + (uint32_t)(stage * BN * BKT + row * BKT + sc) * 2,
                 B + (size_t)(bn + row) * K + kbase + chk * 8);
        }
    };

    issue(0, 0); cp_commit();
    issue(1, 1); cp_commit();

    for (int it = 0; it < NIT; it++) {
        const int s = it % STAGES;
        cp_wait<1>();
        __syncthreads();

        if (it + 2 < NIT) issue((it + 2) % STAGES, it + 2);
        cp_commit();

        const __half* Ast = AsBase + s * BM * BKT;
        const __half* Bst = BsBase + s * BN * BKT;

        uint32_t af[2][4][4], bf[2][16];

        auto ldfrag = [&](int buf, int kc) {
#pragma unroll
            for (int im = 0; im < 4; im++) {
                int row = a_row_l + im * 16;
                int chk = kc + a_chk_l;
                ldsm_x4(af[buf][im], Ast + row * BKT + ((chk ^ (row & 7)) * 8));
            }
#pragma unroll
            for (int n16 = 0; n16 < 4; n16++) {
                int row = b_row_l + n16 * 16;
                int chk = kc + b_chk_l;
                ldsm_x4(bf[buf] + n16 * 4, Bst + row * BKT + ((chk ^ (row & 7)) * 8));
            }
        };

        ldfrag(0, 0);
#pragma unroll
        for (int ks = 0; ks < 4; ks++) {
            const int cur = ks & 1;
            if (ks < 3) ldfrag(cur ^ 1, (ks + 1) * 2);
#pragma unroll
            for (int im = 0; im < 4; im++)
#pragma unroll
                for (int in = 0; in < 8; in++)
                    mma_f16(acc[im][in], af[cur][im], bf[cur] + in * 2);
        }
    }

#pragma unroll
    for (int im = 0; im < 4; im++) {
#pragma unroll
        for (int in = 0; in < 8; in++) {
            int r = bm + wm + im * 16 + g;
            int c = bn + wn + in * 8 + t4 * 2;
            float b0 = bias[c];
            float b1 = bias[c + 1];
            float v00 = acc[im][in][0] + b0, v01 = acc[im][in][1] + b1;
            float v10 = acc[im][in][2] + b0, v11 = acc[im][in][3] + b1;
            if constexpr (sizeof(OutT) == 4) {
                *(float2*)((float*)C + (size_t)r * N + c)       = make_float2(v00, v01);
                *(float2*)((float*)C + (size_t)(r + 8) * N + c) = make_float2(v10, v11);
            } else {
                *(__half2*)((__half*)C + (size_t)r * N + c)       = __floats2half2_rn(v00, v01);
                *(__half2*)((__half*)C + (size_t)(r + 8) * N + c) = __floats2half2_rn(v10, v11);
            }
        }
    }
}

// ---------------------------------------------------------------------------
// Kernel 3: tensor-core attention. One block (128 thr, 4 warps) per (b,h).
// bh0: global (window,head) offset of this chunk.
// ---------------------------------------------------------------------------
__global__ __launch_bounds__(128)
void attn_mma_kernel(__half* __restrict__ out, int bh0)
{
    const int bh = bh0 + blockIdx.x;
    const int b  = bh >> 4;
    const int h  = bh & 15;
    const int w  = b % NW;

    __shared__ __half Qs[64][40];
    __shared__ __half Ks[64][40];
    __shared__ __half Vs[64][40];

    const int tid  = threadIdx.x;
    const int warp = tid >> 5;
    const int lane = tid & 31;

    {
        const __half* base = g_qkvh + (size_t)b * NTOK * QKVN + h * HD;
        int tok = tid >> 1;
        int p   = tid & 1;
        const uint4* qp = (const uint4*)(base + (size_t)tok * QKVN);
        const uint4* kp = (const uint4*)(base + (size_t)tok * QKVN + 512);
        const uint4* vp = (const uint4*)(base + (size_t)tok * QKVN + 1024);
        *(uint4*)&Qs[tok][p * 16 + 0] = qp[p * 2 + 0];
        *(uint4*)&Qs[tok][p * 16 + 8] = qp[p * 2 + 1];
        *(uint4*)&Ks[tok][p * 16 + 0] = kp[p * 2 + 0];
        *(uint4*)&Ks[tok][p * 16 + 8] = kp[p * 2 + 1];
        *(uint4*)&Vs[tok][p * 16 + 0] = vp[p * 2 + 0];
        *(uint4*)&Vs[tok][p * 16 + 8] = vp[p * 2 + 1];
    }
    __syncthreads();

    {
        int r = tid & 63;
        __half* row = (tid < 64) ? Qs[r] : Ks[r];
        float f[32];
        float s = 0.f;
#pragma unroll
        for (int i = 0; i < 16; i++) {
            float2 v = __half22float2(*(__half2*)&row[i * 2]);
            f[i * 2] = v.x; f[i * 2 + 1] = v.y;
            s += v.x * v.x + v.y * v.y;
        }
        float inv = 1.0f / fmaxf(sqrtf(s), 1e-12f);
        if (tid < 64) inv *= g_scale[h];
#pragma unroll
        for (int i = 0; i < 16; i++)
            *(__half2*)&row[i * 2] = __floats2half2_rn(f[i * 2] * inv, f[i * 2 + 1] * inv);
    }
    __syncthreads();

    const int lt = lane >> 3;
    const int lr = lane & 7;
    const int g  = lane >> 2;
    const int t4 = lane & 3;
    const int r0 = warp * 16;
    const int r_lo = r0 + g;
    const int r_hi = r0 + 8 + g;

    // prefetch bias+mask into registers (overlaps with S MMAs below)
    const float* bmp = g_bm + (((size_t)h * NW + w) << 12);
    float2 blo[8], bhi[8];
#pragma unroll
    for (int t = 0; t < 8; t++) {
        int col = t * 8 + t4 * 2;
        blo[t] = *(const float2*)&bmp[r_lo * 64 + col];
        bhi[t] = *(const float2*)&bmp[r_hi * 64 + col];
    }

    float sacc[8][4];
#pragma unroll
    for (int t = 0; t < 8; t++)
#pragma unroll
        for (int r = 0; r < 4; r++) sacc[t][r] = 0.f;

#pragma unroll
    for (int ks = 0; ks < 2; ks++) {
        uint32_t af[4];
        ldsm_x4(af, &Qs[r0 + (lt & 1) * 8 + lr][(lt >> 1) * 8 + ks * 16]);
#pragma unroll
        for (int ng = 0; ng < 4; ng++) {
            uint32_t bfk[4];
            ldsm_x4(bfk, &Ks[ng * 16 + (lt >> 1) * 8 + lr][(lt & 1) * 8 + ks * 16]);
            mma_f16(sacc[ng * 2 + 0], af, bfk);
            mma_f16(sacc[ng * 2 + 1], af, bfk + 2);
        }
    }

#pragma unroll
    for (int t = 0; t < 8; t++) {
        sacc[t][0] += blo[t].x; sacc[t][1] += blo[t].y;
        sacc[t][2] += bhi[t].x; sacc[t][3] += bhi[t].y;
    }

    float mlo = -1e30f, mhi = -1e30f;
#pragma unroll
    for (int t = 0; t < 8; t++) {
        mlo = fmaxf(mlo, fmaxf(sacc[t][0], sacc[t][1]));
        mhi = fmaxf(mhi, fmaxf(sacc[t][2], sacc[t][3]));
    }
    mlo = fmaxf(mlo, __shfl_xor_sync(0xffffffffu, mlo, 1));
    mlo = fmaxf(mlo, __shfl_xor_sync(0xffffffffu, mlo, 2));
    mhi = fmaxf(mhi, __shfl_xor_sync(0xffffffffu, mhi, 1));
    mhi = fmaxf(mhi, __shfl_xor_sync(0xffffffffu, mhi, 2));

    float slo = 0.f, shi = 0.f;
#pragma unroll
    for (int t = 0; t < 8; t++) {
        sacc[t][0] = __expf(sacc[t][0] - mlo);
        sacc[t][1] = __expf(sacc[t][1] - mlo);
        sacc[t][2] = __expf(sacc[t][2] - mhi);
        sacc[t][3] = __expf(sacc[t][3] - mhi);
        slo += sacc[t][0] + sacc[t][1];
        shi += sacc[t][2] + sacc[t][3];
    }
    slo += __shfl_xor_sync(0xffffffffu, slo, 1);
    slo += __shfl_xor_sync(0xffffffffu, slo, 2);
    shi += __shfl_xor_sync(0xffffffffu, shi, 1);
    shi += __shfl_xor_sync(0xffffffffu, shi, 2);
    const float ilo = 1.0f / slo;
    const float ihi = 1.0f / shi;

    uint32_t p01[8], p23[8];
#pragma unroll
    for (int t = 0; t < 8; t++) {
        p01[t] = h2_as_u32(__floats2half2_rn(sacc[t][0] * ilo, sacc[t][1] * ilo));
        p23[t] = h2_as_u32(__floats2half2_rn(sacc[t][2] * ihi, sacc[t][3] * ihi));
    }

    float oacc[4][4];
#pragma unroll
    for (int t = 0; t < 4; t++)
#pragma unroll
        for (int r = 0; r < 4; r++) oacc[t][r] = 0.f;

#pragma unroll
    for (int kg = 0; kg < 4; kg++) {
        uint32_t af[4] = { p01[kg * 2], p23[kg * 2], p01[kg * 2 + 1], p23[kg * 2 + 1] };
        uint32_t bf0[4], bf1[4];
        ldsm_x4_trans(bf0, &Vs[kg * 16 + (lt & 1) * 8 + lr][(lt >> 1) * 8]);
        ldsm_x4_trans(bf1, &Vs[kg * 16 + (lt & 1) * 8 + lr][(lt >> 1) * 8 + 16]);
        mma_f16(oacc[0], af, bf0);
        mma_f16(oacc[1], af, bf0 + 2);
        mma_f16(oacc[2], af, bf1);
        mma_f16(oacc[3], af, bf1 + 2);
    }

    __half* ob = out + ((size_t)b * NTOK) * CDIM + h * HD;
#pragma unroll
    for (int t = 0; t < 4; t++) {
        int col = t * 8 + t4 * 2;
        *(__half2*)(ob + (size_t)r_lo * CDIM + col) = __floats2half2_rn(oacc[t][0], oacc[t][1]);
        *(__half2*)(ob + (size_t)r_hi * CDIM + col) = __floats2half2_rn(oacc[t][2], oacc[t][3]);
    }
}

// ---------------------------------------------------------------------------
// Launch: QKV chunks serial on origin stream (tensor pipe saturated);
// attn chunk c on side stream overlaps QKV chunk c+1 (attn is issue-bound,
// not tensor-bound); proj is ONE serial GEMM at the end (no competition).
// ---------------------------------------------------------------------------
extern "C" void kernel_launch(void* const* d_in, const int* in_sizes, int n_in,
                              void* d_out, int out_size)
{
    const float* x        = (const float*)d_in[0];
    const float* mask     = (const float*)d_in[1];
    const float* qkv_w    = (const float*)d_in[2];
    const float* qkv_b    = (const float*)d_in[3];
    const float* proj_w   = (const float*)d_in[4];
    const float* proj_b   = (const float*)d_in[5];
    const float* t_scale  = (const float*)d_in[6];
    const float* crpb_w1  = (const float*)d_in[7];
    const float* crpb_b1  = (const float*)d_in[8];
    const float* crpb_w2  = (const float*)d_in[9];
    const float* ctable   = (const float*)d_in[10];
    const int*   rel_idx  = (const int*)d_in[11];
    float*       out      = (float*)d_out;

    __half *qkvh, *att, *xh, *wq, *wp;
    cudaGetSymbolAddress((void**)&qkvh, g_qkvh);
    cudaGetSymbolAddress((void**)&att,  g_att);
    cudaGetSymbolAddress((void**)&xh,   g_x);
    cudaGetSymbolAddress((void**)&wq,   g_wq);
    cudaGetSymbolAddress((void**)&wp,   g_wp);

    static bool init_done = false;
    static cudaStream_t s2;
    static cudaEvent_t evQ[NCHUNK], evJoin;
    if (!init_done) {
        cudaFuncSetAttribute(gemm_f16_abT<__half>,
                             cudaFuncAttributeMaxDynamicSharedMemorySize, GEMM_SMEM);
        cudaFuncSetAttribute(gemm_f16_abT<float>,
                             cudaFuncAttributeMaxDynamicSharedMemorySize, GEMM_SMEM);
        cudaStreamCreateWithFlags(&s2, cudaStreamNonBlocking);
        for (int c = 0; c < NCHUNK; c++)
            cudaEventCreateWithFlags(&evQ[c], cudaEventDisableTiming);
        cudaEventCreateWithFlags(&evJoin, cudaEventDisableTiming);
        init_done = true;
    }

    // prep on origin stream
    crpb_tbl_kernel<<<1, 256>>>(ctable, crpb_w1, crpb_b1, crpb_w2, t_scale);
    bm_fill_kernel<<<(HEADS * NW * 4096) / 256, 256>>>(rel_idx, mask);
    {
        int n4x = MTOT * CDIM / 4;
        to_half_kernel<<<(n4x + 255) / 256, 256>>>(x, xh, n4x);
        int n4q = QKVN * CDIM / 4;
        to_half_kernel<<<(n4q + 255) / 256, 256>>>(qkv_w, wq, n4q);
        int n4p = CDIM * CDIM / 4;
        to_half_kernel<<<(n4p + 255) / 256, 256>>>(proj_w, wp, n4p);
    }

    // QKV chunks serial on origin stream; attn chunk c forks to s2
    for (int c = 0; c < NCHUNK; c++) {
        const size_t rowoff = (size_t)c * MCH;
        {
            dim3 grid(QKVN / BN, MCH / BM);
            gemm_f16_abT<__half><<<grid, 128, GEMM_SMEM>>>(
                xh + rowoff * CDIM, wq, qkv_b, qkvh + rowoff * QKVN,
                MCH, QKVN, CDIM);
        }
        cudaEventRecord(evQ[c], 0);
        cudaStreamWaitEvent(s2, evQ[c], 0);
        attn_mma_kernel<<<BCH * HEADS, 128, 0, s2>>>(att, c * BCH * HEADS);
    }

    // join: proj needs all attention output
    cudaEventRecord(evJoin, s2);
    cudaStreamWaitEvent(0, evJoin, 0);

    // proj: one full serial GEMM on origin stream
    {
        dim3 grid(CDIM / BN, MTOT / BM);
        gemm_f16_abT<float><<<grid, 128, GEMM_SMEM>>>(att, wp, proj_b, out,
                                                      MTOT, CDIM, CDIM);
    }
}

// round 16
// speedup vs baseline: 1.0364x; 1.0323x over previous
#include <cuda_runtime.h>
#include <cuda_fp16.h>
#include <cstdint>
#include <cstring>

// ---------------------------------------------------------------------------
// Problem constants
// ---------------------------------------------------------------------------
#define BATCH   1568
#define NTOK    64
#define CDIM    512
#define HEADS   16
#define HD      32
#define NW      49
#define MTOT    (BATCH * NTOK)          // 100352
#define QKVN    (3 * CDIM)              // 1536

// ---------------------------------------------------------------------------
// Device scratch (static globals: allocation-free per harness rules)
// ---------------------------------------------------------------------------
__device__ __half g_qkvh[(size_t)MTOT * QKVN];      // qkv projection output (fp16)
__device__ __half g_att[(size_t)MTOT * CDIM];       // attention output (fp16)
__device__ __half g_x  [(size_t)MTOT * CDIM];       // fp16 input x
__device__ __half g_wq [(size_t)QKVN * CDIM];       // fp16 qkv_w
__device__ __half g_wp [(size_t)CDIM * CDIM];       // fp16 proj_w
__device__ float  g_bm [HEADS * NW * NTOK * NTOK];  // fused bias+mask (h,w,64,64)
__device__ float  g_tbl[225 * HEADS];               // CRPB table
__device__ float  g_scale[HEADS];                   // clamped temperature per head

// ---------------------------------------------------------------------------
// helpers
// ---------------------------------------------------------------------------
__device__ __forceinline__ uint32_t h2_as_u32(__half2 h) {
    uint32_t u;
    memcpy(&u, &h, 4);
    return u;
}

__device__ __forceinline__ void mma_f16(float* c, const uint32_t* a, const uint32_t* b) {
    asm volatile(
        "mma.sync.aligned.m16n8k16.row.col.f32.f16.f16.f32 "
        "{%0,%1,%2,%3}, {%4,%5,%6,%7}, {%8,%9}, {%0,%1,%2,%3};"
        : "+f"(c[0]), "+f"(c[1]), "+f"(c[2]), "+f"(c[3])
        : "r"(a[0]), "r"(a[1]), "r"(a[2]), "r"(a[3]),
          "r"(b[0]), "r"(b[1]));
}

__device__ __forceinline__ void ldsm_x4(uint32_t* r, const __half* p) {
    uint32_t addr = (uint32_t)__cvta_generic_to_shared(p);
    asm volatile("ldmatrix.sync.aligned.m8n8.x4.shared.b16 {%0,%1,%2,%3}, [%4];"
                 : "=r"(r[0]), "=r"(r[1]), "=r"(r[2]), "=r"(r[3]) : "r"(addr));
}

__device__ __forceinline__ void ldsm_x4_trans(uint32_t* r, const __half* p) {
    uint32_t addr = (uint32_t)__cvta_generic_to_shared(p);
    asm volatile("ldmatrix.sync.aligned.m8n8.x4.trans.shared.b16 {%0,%1,%2,%3}, [%4];"
                 : "=r"(r[0]), "=r"(r[1]), "=r"(r[2]), "=r"(r[3]) : "r"(addr));
}

__device__ __forceinline__ void cp16(uint32_t saddr, const void* g) {
    asm volatile("cp.async.ca.shared.global [%0], [%1], 16;" :: "r"(saddr), "l"(g));
}
__device__ __forceinline__ void cp_commit() {
    asm volatile("cp.async.commit_group;");
}
template <int N>
__device__ __forceinline__ void cp_wait() {
    asm volatile("cp.async.wait_group %0;" :: "n"(N));
}

// sum of squares (fp32) of the 16 halves packed in two uint4
__device__ __forceinline__ float ssq16(uint4 a, uint4 b) {
    float s = 0.f;
    const uint32_t* u = &a.x;
#pragma unroll
    for (int i = 0; i < 4; i++) {
        __half2 h; memcpy(&h, &u[i], 4);
        float2 f = __half22float2(h);
        s += f.x * f.x + f.y * f.y;
    }
    const uint32_t* v = &b.x;
#pragma unroll
    for (int i = 0; i < 4; i++) {
        __half2 h; memcpy(&h, &v[i], 4);
        float2 f = __half22float2(h);
        s += f.x * f.x + f.y * f.y;
    }
    return s;
}

// ---------------------------------------------------------------------------
// Kernel 0: fused elementwise fp32 -> fp16 conversion over three buffers
// ---------------------------------------------------------------------------
__global__ void to_half3_kernel(const float* __restrict__ a, __half* __restrict__ ah, int n1,
                                const float* __restrict__ b, __half* __restrict__ bh, int n2,
                                const float* __restrict__ c, __half* __restrict__ ch, int n3)
{
    int i = blockIdx.x * blockDim.x + threadIdx.x;
    const float* src;
    __half* dst;
    int j;
    if (i < n1)                { src = a; dst = ah; j = i; }
    else if (i < n1 + n2)      { src = b; dst = bh; j = i - n1; }
    else if (i < n1 + n2 + n3) { src = c; dst = ch; j = i - n1 - n2; }
    else return;
    float4 v = ((const float4*)src)[j];
    ((__half2*)dst)[j * 2 + 0] = __floats2half2_rn(v.x, v.y);
    ((__half2*)dst)[j * 2 + 1] = __floats2half2_rn(v.z, v.w);
}

// ---------------------------------------------------------------------------
// Kernel 1a: CRPB MLP table + temperature scale
// ---------------------------------------------------------------------------
__global__ void crpb_tbl_kernel(const float* __restrict__ ct,
                                const float* __restrict__ w1,
                                const float* __restrict__ b1,
                                const float* __restrict__ w2,
                                const float* __restrict__ ts)
{
    int e = threadIdx.x;
    if (e < HEADS) {
        g_scale[e] = expf(fminf(ts[e], 4.6051701859880913680f));
    }
    if (e < 225) {
        float c0 = ct[e * 2 + 0];
        float c1 = ct[e * 2 + 1];
        float acc[HEADS];
#pragma unroll
        for (int h = 0; h < HEADS; h++) acc[h] = 0.f;
        for (int j = 0; j < 384; j++) {
            float hv = fmaxf(w1[j * 2 + 0] * c0 + w1[j * 2 + 1] * c1 + b1[j], 0.f);
#pragma unroll
            for (int h = 0; h < HEADS; h++) acc[h] += w2[h * 384 + j] * hv;
        }
#pragma unroll
        for (int h = 0; h < HEADS; h++) g_tbl[e * HEADS + h] = acc[h];
    }
}

// ---------------------------------------------------------------------------
// Kernel 1b: fused bias+mask table
// ---------------------------------------------------------------------------
__global__ void bm_fill_kernel(const int* __restrict__ ridx,
                               const float* __restrict__ mask)
{
    int t = blockIdx.x * blockDim.x + threadIdx.x;
    int ij = t & 4095;
    int hw = t >> 12;
    int w  = hw % NW;
    int h  = hw / NW;
    float v = g_tbl[ridx[ij] * HEADS + h];
    g_bm[t] = 16.f / (1.f + __expf(-v)) + mask[w * 4096 + ij];
}

// ---------------------------------------------------------------------------
// Kernel 2/4: fp16 mma.sync GEMM (fp32 accumulate), templated output type.
// (identical math to R13 passing version)
// ---------------------------------------------------------------------------
#define BM 128
#define BN 128
#define BKT 64
#define STAGES 3
#define GEMM_SMEM (STAGES * (BM + BN) * BKT * 2)   // 98304 bytes

template <typename OutT>
__global__ __launch_bounds__(128, 2)
void gemm_f16_abT(const __half* __restrict__ A, const __half* __restrict__ B,
                  const float* __restrict__ bias, OutT* __restrict__ C,
                  int M, int N, int K)
{
    extern __shared__ __half smh[];
    __half* AsBase = smh;
    __half* BsBase = smh + STAGES * BM * BKT;
    const uint32_t smemA_u32 = (uint32_t)__cvta_generic_to_shared(AsBase);
    const uint32_t smemB_u32 = (uint32_t)__cvta_generic_to_shared(BsBase);

    const int tid  = threadIdx.x;
    const int bm   = blockIdx.y * BM;
    const int bn   = blockIdx.x * BN;
    const int warp = tid >> 5;
    const int lane = tid & 31;
    const int wm   = (warp & 1) * 64;
    const int wn   = (warp >> 1) * 64;
    const int g    = lane >> 2;
    const int t4   = lane & 3;

    const int lt = lane >> 3;
    const int lr = lane & 7;
    const int a_row_l = wm + (lt & 1) * 8 + lr;
    const int a_chk_l = lt >> 1;
    const int b_row_l = wn + (lt >> 1) * 8 + lr;
    const int b_chk_l = lt & 1;

    float acc[4][8][4];
#pragma unroll
    for (int im = 0; im < 4; im++)
#pragma unroll
        for (int in = 0; in < 8; in++)
#pragma unroll
            for (int r = 0; r < 4; r++) acc[im][in][r] = 0.f;

    const int NIT = K / BKT;

    auto issue = [&](int stage, int kt) {
        const int kbase = kt * BKT;
#pragma unroll
        for (int l = 0; l < 8; l++) {
            int f    = tid + l * 128;
            int row  = f >> 3;
            int chk  = f & 7;
            int sc   = (chk ^ (row & 7)) * 8;
            cp16(smemA_u32 + (uint32_t)(stage * BM * BKT + row * BKT + sc) * 2,
                 A + (size_t)(bm + row) * K + kbase + chk * 8);
            cp16(smemB_u32 + (uint32_t)(stage * BN * BKT + row * BKT + sc) * 2,
                 B + (size_t)(bn + row) * K + kbase + chk * 8);
        }
    };

    issue(0, 0); cp_commit();
    issue(1, 1); cp_commit();

    for (int it = 0; it < NIT; it++) {
        const int s = it % STAGES;
        cp_wait<1>();
        __syncthreads();

        if (it + 2 < NIT) issue((it + 2) % STAGES, it + 2);
        cp_commit();

        const __half* Ast = AsBase + s * BM * BKT;
        const __half* Bst = BsBase + s * BN * BKT;

        uint32_t af[2][4][4], bf[2][16];

        auto ldfrag = [&](int buf, int kc) {
#pragma unroll
            for (int im = 0; im < 4; im++) {
                int row = a_row_l + im * 16;
                int chk = kc + a_chk_l;
                ldsm_x4(af[buf][im], Ast + row * BKT + ((chk ^ (row & 7)) * 8));
            }
#pragma unroll
            for (int n16 = 0; n16 < 4; n16++) {
                int row = b_row_l + n16 * 16;
                int chk = kc + b_chk_l;
                ldsm_x4(bf[buf] + n16 * 4, Bst + row * BKT + ((chk ^ (row & 7)) * 8));
            }
        };

        ldfrag(0, 0);
#pragma unroll
        for (int ks = 0; ks < 4; ks++) {
            const int cur = ks & 1;
            if (ks < 3) ldfrag(cur ^ 1, (ks + 1) * 2);
#pragma unroll
            for (int im = 0; im < 4; im++)
#pragma unroll
                for (int in = 0; in < 8; in++)
                    mma_f16(acc[im][in], af[cur][im], bf[cur] + in * 2);
        }
    }

#pragma unroll
    for (int im = 0; im < 4; im++) {
#pragma unroll
        for (int in = 0; in < 8; in++) {
            int r = bm + wm + im * 16 + g;
            int c = bn + wn + in * 8 + t4 * 2;
            float b0 = bias[c];
            float b1 = bias[c + 1];
            float v00 = acc[im][in][0] + b0, v01 = acc[im][in][1] + b1;
            float v10 = acc[im][in][2] + b0, v11 = acc[im][in][3] + b1;
            if constexpr (sizeof(OutT) == 4) {
                *(float2*)((float*)C + (size_t)r * N + c)       = make_float2(v00, v01);
                *(float2*)((float*)C + (size_t)(r + 8) * N + c) = make_float2(v10, v11);
            } else {
                *(__half2*)((__half*)C + (size_t)r * N + c)       = __floats2half2_rn(v00, v01);
                *(__half2*)((__half*)C + (size_t)(r + 8) * N + c) = __floats2half2_rn(v10, v11);
            }
        }
    }
}

// ---------------------------------------------------------------------------
// Kernel 3: tensor-core attention, normalization folded into load + epilogue.
// One block (128 thr, 4 warps) per (b,h). S = Q K^T on RAW fp16 Q,K; the
// cosine scaling rq[i]*rk[j] (rq also carries the temperature) is applied in
// fp32 on the S fragments. Row norms computed in registers during the load.
// ---------------------------------------------------------------------------
__global__ __launch_bounds__(128)
void attn_mma_kernel(__half* __restrict__ out)
{
    const int bh = blockIdx.x;
    const int b  = bh >> 4;
    const int h  = bh & 15;
    const int w  = b % NW;

    __shared__ __half Qs[64][40];
    __shared__ __half Ks[64][40];
    __shared__ __half Vs[64][40];
    __shared__ float  rqn[64];
    __shared__ float  rkn[64];

    const int tid  = threadIdx.x;
    const int warp = tid >> 5;
    const int lane = tid & 31;

    // ---- load Q,K,V; compute row norms in registers ----
    {
        const __half* base = g_qkvh + (size_t)b * NTOK * QKVN + h * HD;
        int tok = tid >> 1;
        int p   = tid & 1;
        const uint4* qp = (const uint4*)(base + (size_t)tok * QKVN);
        const uint4* kp = (const uint4*)(base + (size_t)tok * QKVN + 512);
        const uint4* vp = (const uint4*)(base + (size_t)tok * QKVN + 1024);
        uint4 q0 = qp[p * 2 + 0], q1 = qp[p * 2 + 1];
        uint4 k0 = kp[p * 2 + 0], k1 = kp[p * 2 + 1];
        uint4 v0 = vp[p * 2 + 0], v1 = vp[p * 2 + 1];
        *(uint4*)&Qs[tok][p * 16 + 0] = q0;
        *(uint4*)&Qs[tok][p * 16 + 8] = q1;
        *(uint4*)&Ks[tok][p * 16 + 0] = k0;
        *(uint4*)&Ks[tok][p * 16 + 8] = k1;
        *(uint4*)&Vs[tok][p * 16 + 0] = v0;
        *(uint4*)&Vs[tok][p * 16 + 8] = v1;

        float sq = ssq16(q0, q1);
        float sk = ssq16(k0, k1);
        sq += __shfl_xor_sync(0xffffffffu, sq, 1);
        sk += __shfl_xor_sync(0xffffffffu, sk, 1);
        if (p == 0) {
            rqn[tok] = g_scale[h] / fmaxf(sqrtf(sq), 1e-12f);
            rkn[tok] = 1.0f / fmaxf(sqrtf(sk), 1e-12f);
        }
    }
    __syncthreads();

    const int lt = lane >> 3;
    const int lr = lane & 7;
    const int g  = lane >> 2;
    const int t4 = lane & 3;
    const int r0 = warp * 16;
    const int r_lo = r0 + g;
    const int r_hi = r0 + 8 + g;

    // ---- prefetch bias+mask into registers (overlaps with S MMAs below) ----
    const float* bmp = g_bm + (((size_t)h * NW + w) << 12);
    float2 blo[8], bhi[8];
#pragma unroll
    for (int t = 0; t < 8; t++) {
        int col = t * 8 + t4 * 2;
        blo[t] = *(const float2*)&bmp[r_lo * 64 + col];
        bhi[t] = *(const float2*)&bmp[r_hi * 64 + col];
    }

    // ---- S = Q K^T on raw fp16 (this warp's 16 rows x 64 cols) ----
    float sacc[8][4];
#pragma unroll
    for (int t = 0; t < 8; t++)
#pragma unroll
        for (int r = 0; r < 4; r++) sacc[t][r] = 0.f;

#pragma unroll
    for (int ks = 0; ks < 2; ks++) {
        uint32_t af[4];
        ldsm_x4(af, &Qs[r0 + (lt & 1) * 8 + lr][(lt >> 1) * 8 + ks * 16]);
#pragma unroll
        for (int ng = 0; ng < 4; ng++) {
            uint32_t bfk[4];
            ldsm_x4(bfk, &Ks[ng * 16 + (lt >> 1) * 8 + lr][(lt & 1) * 8 + ks * 16]);
            mma_f16(sacc[ng * 2 + 0], af, bfk);
            mma_f16(sacc[ng * 2 + 1], af, bfk + 2);
        }
    }

    // ---- cosine scaling + bias+mask, softmax in registers ----
    const float rq_lo = rqn[r_lo];
    const float rq_hi = rqn[r_hi];
#pragma unroll
    for (int t = 0; t < 8; t++) {
        int col = t * 8 + t4 * 2;
        float rk0 = rkn[col];
        float rk1 = rkn[col + 1];
        sacc[t][0] = sacc[t][0] * rq_lo * rk0 + blo[t].x;
        sacc[t][1] = sacc[t][1] * rq_lo * rk1 + blo[t].y;
        sacc[t][2] = sacc[t][2] * rq_hi * rk0 + bhi[t].x;
        sacc[t][3] = sacc[t][3] * rq_hi * rk1 + bhi[t].y;
    }

    float mlo = -1e30f, mhi = -1e30f;
#pragma unroll
    for (int t = 0; t < 8; t++) {
        mlo = fmaxf(mlo, fmaxf(sacc[t][0], sacc[t][1]));
        mhi = fmaxf(mhi, fmaxf(sacc[t][2], sacc[t][3]));
    }
    mlo = fmaxf(mlo, __shfl_xor_sync(0xffffffffu, mlo, 1));
    mlo = fmaxf(mlo, __shfl_xor_sync(0xffffffffu, mlo, 2));
    mhi = fmaxf(mhi, __shfl_xor_sync(0xffffffffu, mhi, 1));
    mhi = fmaxf(mhi, __shfl_xor_sync(0xffffffffu, mhi, 2));

    float slo = 0.f, shi = 0.f;
#pragma unroll
    for (int t = 0; t < 8; t++) {
        sacc[t][0] = __expf(sacc[t][0] - mlo);
        sacc[t][1] = __expf(sacc[t][1] - mlo);
        sacc[t][2] = __expf(sacc[t][2] - mhi);
        sacc[t][3] = __expf(sacc[t][3] - mhi);
        slo += sacc[t][0] + sacc[t][1];
        shi += sacc[t][2] + sacc[t][3];
    }
    slo += __shfl_xor_sync(0xffffffffu, slo, 1);
    slo += __shfl_xor_sync(0xffffffffu, slo, 2);
    shi += __shfl_xor_sync(0xffffffffu, shi, 1);
    shi += __shfl_xor_sync(0xffffffffu, shi, 2);
    const float ilo = 1.0f / slo;
    const float ihi = 1.0f / shi;

    uint32_t p01[8], p23[8];
#pragma unroll
    for (int t = 0; t < 8; t++) {
        p01[t] = h2_as_u32(__floats2half2_rn(sacc[t][0] * ilo, sacc[t][1] * ilo));
        p23[t] = h2_as_u32(__floats2half2_rn(sacc[t][2] * ihi, sacc[t][3] * ihi));
    }

    float oacc[4][4];
#pragma unroll
    for (int t = 0; t < 4; t++)
#pragma unroll
        for (int r = 0; r < 4; r++) oacc[t][r] = 0.f;

#pragma unroll
    for (int kg = 0; kg < 4; kg++) {
        uint32_t af[4] = { p01[kg * 2], p23[kg * 2], p01[kg * 2 + 1], p23[kg * 2 + 1] };
        uint32_t bf0[4], bf1[4];
        ldsm_x4_trans(bf0, &Vs[kg * 16 + (lt & 1) * 8 + lr][(lt >> 1) * 8]);
        ldsm_x4_trans(bf1, &Vs[kg * 16 + (lt & 1) * 8 + lr][(lt >> 1) * 8 + 16]);
        mma_f16(oacc[0], af, bf0);
        mma_f16(oacc[1], af, bf0 + 2);
        mma_f16(oacc[2], af, bf1);
        mma_f16(oacc[3], af, bf1 + 2);
    }

    __half* ob = out + ((size_t)b * NTOK) * CDIM + h * HD;
#pragma unroll
    for (int t = 0; t < 4; t++) {
        int col = t * 8 + t4 * 2;
        *(__half2*)(ob + (size_t)r_lo * CDIM + col) = __floats2half2_rn(oacc[t][0], oacc[t][1]);
        *(__half2*)(ob + (size_t)r_hi * CDIM + col) = __floats2half2_rn(oacc[t][2], oacc[t][3]);
    }
}

// ---------------------------------------------------------------------------
// Launch: serial pipeline (streams proved counterproductive in R14/R15)
// ---------------------------------------------------------------------------
extern "C" void kernel_launch(void* const* d_in, const int* in_sizes, int n_in,
                              void* d_out, int out_size)
{
    const float* x        = (const float*)d_in[0];
    const float* mask     = (const float*)d_in[1];
    const float* qkv_w    = (const float*)d_in[2];
    const float* qkv_b    = (const float*)d_in[3];
    const float* proj_w   = (const float*)d_in[4];
    const float* proj_b   = (const float*)d_in[5];
    const float* t_scale  = (const float*)d_in[6];
    const float* crpb_w1  = (const float*)d_in[7];
    const float* crpb_b1  = (const float*)d_in[8];
    const float* crpb_w2  = (const float*)d_in[9];
    const float* ctable   = (const float*)d_in[10];
    const int*   rel_idx  = (const int*)d_in[11];
    float*       out      = (float*)d_out;

    __half *qkvh, *att, *xh, *wq, *wp;
    cudaGetSymbolAddress((void**)&qkvh, g_qkvh);
    cudaGetSymbolAddress((void**)&att,  g_att);
    cudaGetSymbolAddress((void**)&xh,   g_x);
    cudaGetSymbolAddress((void**)&wq,   g_wq);
    cudaGetSymbolAddress((void**)&wp,   g_wp);

    static bool attr_set = false;
    if (!attr_set) {
        cudaFuncSetAttribute(gemm_f16_abT<__half>,
                             cudaFuncAttributeMaxDynamicSharedMemorySize, GEMM_SMEM);
        cudaFuncSetAttribute(gemm_f16_abT<float>,
                             cudaFuncAttributeMaxDynamicSharedMemorySize, GEMM_SMEM);
        attr_set = true;
    }

    // 1. CRPB table + scale, fused bias+mask fill
    crpb_tbl_kernel<<<1, 256>>>(ctable, crpb_w1, crpb_b1, crpb_w2, t_scale);
    bm_fill_kernel<<<(HEADS * NW * 4096) / 256, 256>>>(rel_idx, mask);

    // 1b. convert all GEMM operands to fp16 in ONE launch
    {
        int n1 = MTOT * CDIM / 4;
        int n2 = QKVN * CDIM / 4;
        int n3 = CDIM * CDIM / 4;
        int nt = n1 + n2 + n3;
        to_half3_kernel<<<(nt + 255) / 256, 256>>>(x, xh, n1, qkv_w, wq, n2,
                                                   proj_w, wp, n3);
    }

    // 2. QKV projection -> fp16
    {
        dim3 grid(QKVN / BN, MTOT / BM);
        gemm_f16_abT<__half><<<grid, 128, GEMM_SMEM>>>(xh, wq, qkv_b, qkvh,
                                                       MTOT, QKVN, CDIM);
    }

    // 3. tensor-core attention (fp16 in/out), norm folded
    attn_mma_kernel<<<BATCH * HEADS, 128>>>(att);

    // 4. output projection -> fp32 d_out
    {
        dim3 grid(CDIM / BN, MTOT / BM);
        gemm_f16_abT<float><<<grid, 128, GEMM_SMEM>>>(att, wp, proj_b, out,
                                                      MTOT, CDIM, CDIM);
    }
}